// round 4
// baseline (speedup 1.0000x reference)
#include <cuda_runtime.h>
#include <cuda_bf16.h>
#include <cstdint>

// GoalDecoderLSTM, B=131072, H=64, E=16, SEQ=30 — HMMA (mma.sync bf16), occ-2 version.
// CTA = 64 elems, 4 warps (mw=wid&1 rows, nw=wid>>1 gate-cols), 2 CTAs/SM.
// D[64,256] = A[64,80] @ B[256,80]^T per step, 3-term bf16 split.
// Single H buffer (bf16x2 hi/lo images, HROW=40, fragment-permuted word order),
// 3 barriers/step: [A-loads | mma+h' writes+RELP | rel/out/x' writes].

#define TB    64
#define SEQ   30
#define NTHR  128
#define HROW  40

// SMEM byte offsets
#define SM_BFRAG   0                        // 320 frags * 256B = 81920
#define SM_H       81920                    // hi 10240 + lo 10240
#define SM_F       102400
// float indices within sF
#define FI_BC    0      // 256
#define FI_W2P   256    // 128
#define FI_MG    384    // 128
#define FI_M2    512    // 4
#define FI_CV    516    // 2
#define FI_CG    518    // 2
#define FI_WSE4  520    // 32
#define FI_BSE2  552    // 16
#define FI_RELP  568    // 128
#define SF_FLOATS 696
#define SMEM_BYTES (SM_F + SF_FLOATS*4)     // 105184

typedef uint32_t u32;
typedef unsigned long long u64;

// ---- device staging (prep -> main) ----
__device__ __align__(16) u64 g_Bfrag[320 * 32];   // 81920 B, t-pair interleaved
__device__ float g_bc[256];
__device__ float g_w2p[128];
__device__ float g_Mg[128];
__device__ float g_M2[4];
__device__ float g_cv[2];
__device__ float g_cg[2];
__device__ float g_wse4[32];
__device__ float g_bse2[16];

// ---- helpers ----
__device__ __forceinline__ u32 pack_bf16(float lo, float hi) {
    u32 r;
    asm("cvt.rn.bf16x2.f32 %0, %1, %2;" : "=r"(r) : "f"(hi), "f"(lo));
    return r;
}
__device__ __forceinline__ void bf16_split(float a, float b, u32& hi, u32& lo) {
    hi = pack_bf16(a, b);
    float ra = a - __uint_as_float(hi << 16);
    float rb = b - __uint_as_float(hi & 0xFFFF0000u);
    lo = pack_bf16(ra, rb);
}
__device__ __forceinline__ void mma16816(float* d, const u32* a, u32 b0, u32 b1) {
    asm volatile("mma.sync.aligned.m16n8k16.row.col.f32.bf16.bf16.f32 "
        "{%0,%1,%2,%3}, {%4,%5,%6,%7}, {%8,%9}, {%0,%1,%2,%3};"
        : "+f"(d[0]), "+f"(d[1]), "+f"(d[2]), "+f"(d[3])
        : "r"(a[0]), "r"(a[1]), "r"(a[2]), "r"(a[3]), "r"(b0), "r"(b1));
}
__device__ __forceinline__ float sigf(float x) {
    return __fdividef(1.0f, 1.0f + __expf(-x));
}
__device__ __forceinline__ float tanh_fast(float x) {
    float ax = fabsf(x);
    float e  = __expf(-2.0f * ax);
    float t  = __fdividef(1.0f - e, 1.0f + e);
    return copysignf(t, x);
}
// fragment-friendly word permutation within each 8-word block:
// logical pos p -> 2*(p&3) + (p>>2), so (p, p+4) land adjacent (LDS.64 pairs)
__device__ __host__ __forceinline__ int permw(int w) {
    return (w & ~7) + 2 * (w & 3) + ((w >> 2) & 1);
}

// ============================================================================
// Prep: fold small matrices; build B fragments (bf16 hi/lo, t-pair interleaved)
// ============================================================================
__global__ void prep_kernel(const float* __restrict__ W_ih, const float* __restrict__ W_hh,
                            const float* __restrict__ b_ih, const float* __restrict__ b_hh,
                            const float* __restrict__ W_h2p, const float* __restrict__ b_h2p,
                            const float* __restrict__ W_goal, const float* __restrict__ b_goal,
                            const float* __restrict__ W_abs, const float* __restrict__ b_abs,
                            const float* __restrict__ W_se, const float* __restrict__ b_se)
{
    int tid = threadIdx.x;
    for (int idx = tid; idx < 320 * 32; idx += NTHR) {
        int f = idx >> 5, l = idx & 31;
        int t = f & 3, kc = (f >> 2) % 5, g = (f / 20) & 3, nw = (f / 80) & 1, img = f / 160;
        int jj = l >> 2, c4 = l & 3;
        int j = 32 * nw + 8 * g + jj;
        int row = t * 64 + j;
        int k0 = 16 * kc + 2 * c4;
        float v[4];
        #pragma unroll
        for (int i = 0; i < 4; i++) {
            int k = k0 + (i & 1) + (i >> 1) * 8;
            v[i] = (k < 64) ? W_hh[row * 64 + k] : W_ih[row * 16 + (k - 64)];
        }
        u32 w0, w1;
        if (img == 0) {
            __nv_bfloat16 a = __float2bfloat16(v[0]), b = __float2bfloat16(v[1]);
            __nv_bfloat16 c = __float2bfloat16(v[2]), d = __float2bfloat16(v[3]);
            w0 = (u32)*(uint16_t*)&a | ((u32)*(uint16_t*)&b << 16);
            w1 = (u32)*(uint16_t*)&c | ((u32)*(uint16_t*)&d << 16);
        } else {
            float r[4];
            #pragma unroll
            for (int i = 0; i < 4; i++) {
                __nv_bfloat16 h = __float2bfloat16(v[i]);
                r[i] = v[i] - __bfloat162float(h);
            }
            __nv_bfloat16 a = __float2bfloat16(r[0]), b = __float2bfloat16(r[1]);
            __nv_bfloat16 c = __float2bfloat16(r[2]), d = __float2bfloat16(r[3]);
            w0 = (u32)*(uint16_t*)&a | ((u32)*(uint16_t*)&b << 16);
            w1 = (u32)*(uint16_t*)&c | ((u32)*(uint16_t*)&d << 16);
        }
        // dest: t-pair interleave for LDS.128
        int fbase = ((((img * 2 + nw) * 4 + g) * 5 + kc) * 2 + (t >> 1));
        g_Bfrag[fbase * 64 + 2 * l + (t & 1)] = (u64)w0 | ((u64)w1 << 32);
    }
    for (int i = tid; i < 256; i += NTHR) {
        int j = i & 63, t = i >> 6, row = t * 64 + j;
        g_bc[i] = b_ih[row] + b_hh[row];
    }
    if (tid < 64) {
        g_w2p[2 * tid]     = W_h2p[tid];
        g_w2p[2 * tid + 1] = W_h2p[192 + tid];
    }
    if (tid < 128) {
        int r = tid >> 6, j = tid & 63;
        float s = 0.f;
        for (int m = 0; m < 64; m++) s += W_h2p[r * 192 + 128 + m] * W_goal[m * 64 + j];
        g_Mg[tid] = s;
    }
    if (tid < 4) {
        int r = tid >> 1, c = tid & 1;
        float s = 0.f;
        for (int m = 0; m < 64; m++) s += W_h2p[r * 192 + 64 + m] * W_abs[m * 2 + c];
        g_M2[tid] = s;
    }
    if (tid < 2) {
        float s = b_h2p[tid];
        for (int m = 0; m < 64; m++) s += W_h2p[tid * 192 + 64 + m] * b_abs[m];
        g_cv[tid] = s;
        float s2 = 0.f;
        for (int m = 0; m < 64; m++) s2 += W_h2p[tid * 192 + 128 + m] * b_goal[m];
        g_cg[tid] = s2;
    }
    if (tid < 8) {
        g_wse4[tid * 4 + 0] = W_se[(2 * tid) * 2 + 0];
        g_wse4[tid * 4 + 1] = W_se[(2 * tid) * 2 + 1];
        g_wse4[tid * 4 + 2] = W_se[(2 * tid + 1) * 2 + 0];
        g_wse4[tid * 4 + 3] = W_se[(2 * tid + 1) * 2 + 1];
        g_bse2[tid * 2 + 0] = b_se[2 * tid];
        g_bse2[tid * 2 + 1] = b_se[2 * tid + 1];
    }
}

// ============================================================================
// Main kernel: 64 elems / CTA, 4 warps, 2 CTAs per SM
// ============================================================================
__global__ void __launch_bounds__(NTHR, 2)
lstm_main(const float* __restrict__ traj_abs, const float* __restrict__ traj_rel,
          const float* __restrict__ h0g, const float* __restrict__ c0g,
          const float* __restrict__ goals, float* __restrict__ out, int Btot)
{
    extern __shared__ __align__(16) char smem[];
    float* sF = (float*)(smem + SM_F);
    const int tid = threadIdx.x, l = tid & 31, wid = tid >> 5;
    const int mw = wid & 1, nw = wid >> 1;
    const int c4 = l & 3, q = l >> 2;
    const int b0 = blockIdx.x * TB;

    // ---- copy staged weights into SMEM ----
    {
        const float4* src = (const float4*)g_Bfrag;
        float4* dst = (float4*)(smem + SM_BFRAG);
        for (int i = tid; i < 5120; i += NTHR) dst[i] = src[i];
    }
    for (int i = tid; i < 256; i += NTHR) sF[FI_BC + i] = g_bc[i];
    for (int i = tid; i < 128; i += NTHR) { sF[FI_W2P + i] = g_w2p[i]; sF[FI_MG + i] = g_Mg[i]; }
    if (tid < 4)  sF[FI_M2 + tid] = g_M2[tid];
    if (tid < 2)  { sF[FI_CV + tid] = g_cv[tid]; sF[FI_CG + tid] = g_cg[tid]; }
    if (tid < 32) sF[FI_WSE4 + tid] = g_wse4[tid];
    if (tid < 16) sF[FI_BSE2 + tid] = g_bse2[tid];
    __syncthreads();

    // ---- init H buffer from h0, x0 (permuted word layout) ----
    u32* Hhi = (u32*)(smem + SM_H);
    u32* Hlo = Hhi + TB * HROW;
    for (int idx = tid; idx < TB * 32; idx += NTHR) {
        int row = idx >> 5, w = idx & 31;
        float2 hv = *(const float2*)(h0g + (size_t)(b0 + row) * 64 + 2 * w);
        u32 hw, lw; bf16_split(hv.x, hv.y, hw, lw);
        int widx = row * HROW + permw(w);
        Hhi[widx] = hw; Hlo[widx] = lw;
    }
    for (int idx = tid; idx < TB * 8; idx += NTHR) {
        int row = idx >> 3, p = idx & 7;
        float2 tr = *(const float2*)(traj_rel + (size_t)(b0 + row) * 2);
        float4 w4 = *(const float4*)(sF + FI_WSE4 + 4 * p);
        float xa = w4.x * tr.x + w4.y * tr.y + sF[FI_BSE2 + 2 * p];
        float xb = w4.z * tr.x + w4.w * tr.y + sF[FI_BSE2 + 2 * p + 1];
        xa = (xa > 0.f) ? xa : 0.01f * xa;
        xb = (xb > 0.f) ? xb : 0.01f * xb;
        u32 hw, lw; bf16_split(xa, xb, hw, lw);
        int widx = row * HROW + 32 + 2 * (p & 3) + (p >> 2);
        Hhi[widx] = hw; Hlo[widx] = lw;
    }

    // ---- c-state into registers: creg[g][m][rh][jj] ----
    float creg[4][2][2][2];
    #pragma unroll
    for (int g = 0; g < 4; g++)
        #pragma unroll
        for (int m = 0; m < 2; m++)
            #pragma unroll
            for (int rh = 0; rh < 2; rh++) {
                int row = 32 * mw + 16 * m + 8 * rh + q;
                int j = 32 * nw + 8 * g + 2 * c4;
                float2 cv2 = *(const float2*)(c0g + (size_t)(b0 + row) * 64 + j);
                creg[g][m][rh][0] = cv2.x; creg[g][m][rh][1] = cv2.y;
            }

    // ---- per-row derived state (nw==0 warps) ----
    float goc[4][2], ab[4][2];
    if (nw == 0) {
        #pragma unroll
        for (int m = 0; m < 2; m++)
            #pragma unroll
            for (int rh = 0; rh < 2; rh++) {
                int rl = 2 * m + rh;
                int row = 32 * mw + 16 * m + 8 * rh + q;
                ab[rl][0] = traj_abs[(size_t)(b0 + row) * 2];
                ab[rl][1] = traj_abs[(size_t)(b0 + row) * 2 + 1];
                float s0 = sF[FI_CG], s1 = sF[FI_CG + 1];
                const float* gp = goals + (size_t)(b0 + row) * 64;
                #pragma unroll 8
                for (int k = 0; k < 64; k++) {
                    float gv = gp[k];
                    s0 += sF[FI_MG + k] * gv;
                    s1 += sF[FI_MG + 64 + k] * gv;
                }
                goc[rl][0] = s0; goc[rl][1] = s1;
            }
    }
    __syncthreads();

    const u64* BfragS = (const u64*)(smem + SM_BFRAG);

    for (int s = 0; s < SEQ; s++) {
        // ---- load A fragments (hi/lo), conflict-free LDS.64 ----
        u32 Ahi[2][5][4], Alo[2][5][4];
        #pragma unroll
        for (int m = 0; m < 2; m++) {
            const int rbase = (32 * mw + 16 * m + q) * HROW;
            #pragma unroll
            for (int kc = 0; kc < 5; kc++) {
                int base = rbase + 8 * kc + 2 * c4;
                u64 v0 = *(const u64*)(Hhi + base);
                u64 v1 = *(const u64*)(Hhi + base + 8 * HROW);
                Ahi[m][kc][0] = (u32)v0; Ahi[m][kc][2] = (u32)(v0 >> 32);
                Ahi[m][kc][1] = (u32)v1; Ahi[m][kc][3] = (u32)(v1 >> 32);
                u64 w0 = *(const u64*)(Hlo + base);
                u64 w1 = *(const u64*)(Hlo + base + 8 * HROW);
                Alo[m][kc][0] = (u32)w0; Alo[m][kc][2] = (u32)(w0 >> 32);
                Alo[m][kc][1] = (u32)w1; Alo[m][kc][3] = (u32)(w1 >> 32);
            }
        }
        __syncthreads();   // [A] all loads done before any h' write

        float rp[4][2] = {};
        #pragma unroll
        for (int g = 0; g < 4; g++) {
            float acc[2][4][4] = {};
            #pragma unroll
            for (int kc = 0; kc < 5; kc++) {
                const int i0 = ((nw * 4 + g) * 5 + kc) * 2;        // img0
                const int i1 = (((2 + nw) * 4 + g) * 5 + kc) * 2;  // img1
                ulonglong2 Bh01 = *(const ulonglong2*)(BfragS + i0 * 64 + 2 * l);
                ulonglong2 Bh23 = *(const ulonglong2*)(BfragS + (i0 + 1) * 64 + 2 * l);
                ulonglong2 Bl01 = *(const ulonglong2*)(BfragS + i1 * 64 + 2 * l);
                ulonglong2 Bl23 = *(const ulonglong2*)(BfragS + (i1 + 1) * 64 + 2 * l);
                u64 bhv[4] = { Bh01.x, Bh01.y, Bh23.x, Bh23.y };
                u64 blv[4] = { Bl01.x, Bl01.y, Bl23.x, Bl23.y };
                #pragma unroll
                for (int t = 0; t < 4; t++) {
                    u32 bh0 = (u32)bhv[t], bh1 = (u32)(bhv[t] >> 32);
                    u32 bl0 = (u32)blv[t], bl1 = (u32)(blv[t] >> 32);
                    #pragma unroll
                    for (int m = 0; m < 2; m++) {
                        mma16816(acc[m][t], Ahi[m][kc], bh0, bh1);
                        mma16816(acc[m][t], Alo[m][kc], bh0, bh1);
                        mma16816(acc[m][t], Ahi[m][kc], bl0, bl1);
                    }
                }
            }
            // ---- epilogue for gate-group g ----
            const int jbase = 32 * nw + 8 * g + 2 * c4;
            const float2 bI = *(const float2*)(sF + FI_BC + jbase);
            const float2 bF = *(const float2*)(sF + FI_BC + 64 + jbase);
            const float2 bG = *(const float2*)(sF + FI_BC + 128 + jbase);
            const float2 bO = *(const float2*)(sF + FI_BC + 192 + jbase);
            const float4 w2q = *(const float4*)(sF + FI_W2P + 2 * jbase);
            const int wl = 16 * nw + 4 * g + c4;
            const int widx = (wl & ~7) + 2 * (wl & 3) + ((wl >> 2) & 1);
            #pragma unroll
            for (int m = 0; m < 2; m++) {
                #pragma unroll
                for (int rh = 0; rh < 2; rh++) {
                    const int rl = 2 * m + rh;
                    float iv0 = acc[m][0][2 * rh] + bI.x, iv1 = acc[m][0][2 * rh + 1] + bI.y;
                    float fv0 = acc[m][1][2 * rh] + bF.x, fv1 = acc[m][1][2 * rh + 1] + bF.y;
                    float gv0 = acc[m][2][2 * rh] + bG.x, gv1 = acc[m][2][2 * rh + 1] + bG.y;
                    float ov0 = acc[m][3][2 * rh] + bO.x, ov1 = acc[m][3][2 * rh + 1] + bO.y;
                    float cn0 = sigf(fv0) * creg[g][m][rh][0] + sigf(iv0) * tanh_fast(gv0);
                    float cn1 = sigf(fv1) * creg[g][m][rh][1] + sigf(iv1) * tanh_fast(gv1);
                    creg[g][m][rh][0] = cn0; creg[g][m][rh][1] = cn1;
                    float h0v = sigf(ov0) * tanh_fast(cn0);
                    float h1v = sigf(ov1) * tanh_fast(cn1);
                    rp[rl][0] += w2q.x * h0v + w2q.z * h1v;
                    rp[rl][1] += w2q.y * h0v + w2q.w * h1v;
                    u32 hw, lw; bf16_split(h0v, h1v, hw, lw);
                    const int row = 32 * mw + 16 * m + 8 * rh + q;
                    Hhi[row * HROW + widx] = hw;
                    Hlo[row * HROW + widx] = lw;
                }
            }
        }

        // ---- rel partial reduction within quads ----
        #pragma unroll
        for (int rl = 0; rl < 4; rl++) {
            #pragma unroll
            for (int ax = 0; ax < 2; ax++) {
                float v = rp[rl][ax];
                v += __shfl_xor_sync(0xFFFFFFFFu, v, 1);
                v += __shfl_xor_sync(0xFFFFFFFFu, v, 2);
                rp[rl][ax] = v;
            }
        }
        if (nw == 1 && c4 == 0) {
            #pragma unroll
            for (int rl = 0; rl < 4; rl++) {
                int row = 32 * mw + 16 * (rl >> 1) + 8 * (rl & 1) + q;
                *(float2*)(sF + FI_RELP + 2 * row) = make_float2(rp[rl][0], rp[rl][1]);
            }
        }
        __syncthreads();   // [B] h' writes + RELP visible

        if (nw == 0) {
            #pragma unroll
            for (int rl = 0; rl < 4; rl++) {
                const int row = 32 * mw + 16 * (rl >> 1) + 8 * (rl & 1) + q;
                float2 pt = *(const float2*)(sF + FI_RELP + 2 * row);
                float r0 = rp[rl][0] + pt.x + sF[FI_CV] + goc[rl][0]
                         + sF[FI_M2] * ab[rl][0] + sF[FI_M2 + 1] * ab[rl][1];
                float r1 = rp[rl][1] + pt.y + sF[FI_CV + 1] + goc[rl][1]
                         + sF[FI_M2 + 2] * ab[rl][0] + sF[FI_M2 + 3] * ab[rl][1];
                if (c4 == 0)
                    *(float2*)(out + ((size_t)s * Btot + b0 + row) * 2) = make_float2(r0, r1);
                ab[rl][0] += r0; ab[rl][1] += r1;
                if (s < SEQ - 1) {
                    #pragma unroll
                    for (int pi = 0; pi < 2; pi++) {
                        int p = c4 + 4 * pi;
                        float4 w4 = *(const float4*)(sF + FI_WSE4 + 4 * p);
                        float xa = w4.x * r0 + w4.y * r1 + sF[FI_BSE2 + 2 * p];
                        float xb = w4.z * r0 + w4.w * r1 + sF[FI_BSE2 + 2 * p + 1];
                        xa = (xa > 0.f) ? xa : 0.01f * xa;
                        xb = (xb > 0.f) ? xb : 0.01f * xb;
                        u32 hw, lw; bf16_split(xa, xb, hw, lw);
                        const int widx = row * HROW + 32 + 2 * c4 + pi;
                        Hhi[widx] = hw;
                        Hlo[widx] = lw;
                    }
                }
            }
        }
        __syncthreads();   // [C] buffer fully updated for next step
    }
}

// ============================================================================
extern "C" void kernel_launch(void* const* d_in, const int* in_sizes, int n_in,
                              void* d_out, int out_size)
{
    const float* traj_abs = (const float*)d_in[0];
    const float* traj_rel = (const float*)d_in[1];
    const float* h0       = (const float*)d_in[2];
    const float* c0       = (const float*)d_in[3];
    const float* goals    = (const float*)d_in[4];
    const float* W_ih     = (const float*)d_in[5];
    const float* W_hh     = (const float*)d_in[6];
    const float* b_ih     = (const float*)d_in[7];
    const float* b_hh     = (const float*)d_in[8];
    const float* W_se     = (const float*)d_in[9];
    const float* b_se     = (const float*)d_in[10];
    const float* W_h2p    = (const float*)d_in[11];
    const float* b_h2p    = (const float*)d_in[12];
    const float* W_goal   = (const float*)d_in[13];
    const float* b_goal   = (const float*)d_in[14];
    const float* W_abs    = (const float*)d_in[15];
    const float* b_abs    = (const float*)d_in[16];

    int B = in_sizes[2] / 64;

    cudaFuncSetAttribute(lstm_main, cudaFuncAttributeMaxDynamicSharedMemorySize, SMEM_BYTES);

    prep_kernel<<<1, NTHR>>>(W_ih, W_hh, b_ih, b_hh, W_h2p, b_h2p,
                             W_goal, b_goal, W_abs, b_abs, W_se, b_se);
    lstm_main<<<B / TB, NTHR, SMEM_BYTES>>>(traj_abs, traj_rel, h0, c0, goals,
                                            (float*)d_out, B);
}

// round 5
// speedup vs baseline: 1.4863x; 1.4863x over previous
#include <cuda_runtime.h>
#include <cuda_fp16.h>
#include <cstdint>

// GoalDecoderLSTM, B=131072, H=64, E=16, SEQ=30 — HMMA fp16 2-term split.
// R3 tiling (128 elems/CTA, 8 warps, occ 1) + warp-staggered gate groups +
// merged-rcp activations. D[128,256] = (Ahi+Alo)[128,80] @ Bf16[256,80]^T.

#define TB    128
#define SEQ   30
#define NTHR  256
#define HROW  44

// SMEM byte offsets
#define SM_BFRAG   0                        // 160 frags * 256B = 40960
#define SM_H       40960                    // 2 bufs * (Hhi 22528 + Hlo 22528)
#define HBUF_BYTES 45056
#define SM_F       (SM_H + 2*HBUF_BYTES)    // 131072
// float indices within sF
#define FI_BC    0      // 256
#define FI_W2P   256    // 128
#define FI_MG    384    // 128
#define FI_M2    512    // 4
#define FI_CV    516    // 2
#define FI_CG    518    // 2
#define FI_WSE4  520    // 32
#define FI_BSE2  552    // 16
#define FI_RELP  568    // 256
#define SF_FLOATS 824
#define SMEM_BYTES (SM_F + SF_FLOATS*4)     // 134368

typedef uint32_t u32;
typedef unsigned long long u64;

// ---- device staging (prep -> main) ----
__device__ __align__(16) u64 g_Bfrag[160 * 32];   // 40960 B
__device__ float g_bc[256];
__device__ float g_w2p[128];
__device__ float g_Mg[128];
__device__ float g_M2[4];
__device__ float g_cv[2];
__device__ float g_cg[2];
__device__ float g_wse4[32];
__device__ float g_bse2[16];

// ---- helpers ----
__device__ __forceinline__ void f16_split(float a, float b, u32& hi, u32& lo) {
    __half2 h = __floats2half2_rn(a, b);        // a -> low, b -> high
    hi = *(u32*)&h;
    float ra = a - __half2float(__low2half(h));
    float rb = b - __half2float(__high2half(h));
    __half2 l2 = __floats2half2_rn(ra, rb);
    lo = *(u32*)&l2;
}
__device__ __forceinline__ void mma16816(float* d, const u32* a, u32 b0, u32 b1) {
    asm volatile("mma.sync.aligned.m16n8k16.row.col.f32.f16.f16.f32 "
        "{%0,%1,%2,%3}, {%4,%5,%6,%7}, {%8,%9}, {%0,%1,%2,%3};"
        : "+f"(d[0]), "+f"(d[1]), "+f"(d[2]), "+f"(d[3])
        : "r"(a[0]), "r"(a[1]), "r"(a[2]), "r"(a[3]), "r"(b0), "r"(b1));
}
// merged-reciprocal LSTM unit: updates c, returns h. 5 ex2 + 2 rcp.
__device__ __forceinline__ float lstm_unit(float iv, float fv, float gv, float ov, float& cst) {
    float ea = __expf(-iv);
    float eb = __expf(-fv);
    float ed = __expf(-2.0f * fabsf(gv));
    float pa = 1.0f + ea, pb = 1.0f + eb, pd = 1.0f + ed;
    float r1 = __fdividef(1.0f, pa * pb * pd);
    float cn = cst * pa * pd * r1 + copysignf((1.0f - ed) * pb * r1, gv);
    cst = cn;
    float eo = __expf(-ov);
    float ee = __expf(-2.0f * fabsf(cn));
    float r2 = __fdividef(1.0f, (1.0f + eo) * (1.0f + ee));
    return copysignf((1.0f - ee) * r2, cn);
}

// ============================================================================
// Prep: fold small matrices; build B fragments (fp16, mma-fragment order)
// ============================================================================
__global__ void prep_kernel(const float* __restrict__ W_ih, const float* __restrict__ W_hh,
                            const float* __restrict__ b_ih, const float* __restrict__ b_hh,
                            const float* __restrict__ W_h2p, const float* __restrict__ b_h2p,
                            const float* __restrict__ W_goal, const float* __restrict__ b_goal,
                            const float* __restrict__ W_abs, const float* __restrict__ b_abs,
                            const float* __restrict__ W_se, const float* __restrict__ b_se)
{
    int tid = threadIdx.x;
    // frag f = ((nw*4+g)*5+kc)*4+t, lane l
    for (int idx = tid; idx < 160 * 32; idx += NTHR) {
        int f = idx >> 5, l = idx & 31;
        int t = f & 3, kc = (f >> 2) % 5, g = (f / 20) & 3, nw = (f / 80) & 1;
        int jj = l >> 2, c4 = l & 3;
        int j = 32 * nw + 8 * g + jj;
        int row = t * 64 + j;
        int k0 = 16 * kc + 2 * c4;
        float v[4];
        #pragma unroll
        for (int i = 0; i < 4; i++) {
            int k = k0 + (i & 1) + (i >> 1) * 8;
            v[i] = (k < 64) ? W_hh[row * 64 + k] : W_ih[row * 16 + (k - 64)];
        }
        __half2 p0 = __floats2half2_rn(v[0], v[1]);
        __half2 p1 = __floats2half2_rn(v[2], v[3]);
        g_Bfrag[idx] = (u64)*(u32*)&p0 | ((u64)*(u32*)&p1 << 32);
    }
    {
        int j = tid & 63, t = tid >> 6, row = t * 64 + j;
        g_bc[tid] = b_ih[row] + b_hh[row];
    }
    if (tid < 64) {
        g_w2p[2 * tid]     = W_h2p[tid];
        g_w2p[2 * tid + 1] = W_h2p[192 + tid];
    }
    if (tid < 128) {
        int r = tid >> 6, j = tid & 63;
        float s = 0.f;
        for (int m = 0; m < 64; m++) s += W_h2p[r * 192 + 128 + m] * W_goal[m * 64 + j];
        g_Mg[tid] = s;
    }
    if (tid < 4) {
        int r = tid >> 1, c = tid & 1;
        float s = 0.f;
        for (int m = 0; m < 64; m++) s += W_h2p[r * 192 + 64 + m] * W_abs[m * 2 + c];
        g_M2[tid] = s;
    }
    if (tid < 2) {
        float s = b_h2p[tid];
        for (int m = 0; m < 64; m++) s += W_h2p[tid * 192 + 64 + m] * b_abs[m];
        g_cv[tid] = s;
        float s2 = 0.f;
        for (int m = 0; m < 64; m++) s2 += W_h2p[tid * 192 + 128 + m] * b_goal[m];
        g_cg[tid] = s2;
    }
    if (tid < 8) {
        g_wse4[tid * 4 + 0] = W_se[(2 * tid) * 2 + 0];
        g_wse4[tid * 4 + 1] = W_se[(2 * tid) * 2 + 1];
        g_wse4[tid * 4 + 2] = W_se[(2 * tid + 1) * 2 + 0];
        g_wse4[tid * 4 + 3] = W_se[(2 * tid + 1) * 2 + 1];
        g_bse2[tid * 2 + 0] = b_se[2 * tid];
        g_bse2[tid * 2 + 1] = b_se[2 * tid + 1];
    }
}

// ============================================================================
// Main kernel: 128 elems/CTA, 8 warps
// ============================================================================
__global__ void __launch_bounds__(NTHR, 1)
lstm_main(const float* __restrict__ traj_abs, const float* __restrict__ traj_rel,
          const float* __restrict__ h0g, const float* __restrict__ c0g,
          const float* __restrict__ goals, float* __restrict__ out, int Btot)
{
    extern __shared__ __align__(16) char smem[];
    float* sF = (float*)(smem + SM_F);
    const int tid = threadIdx.x, l = tid & 31, wid = tid >> 5;
    const int mw = wid & 3, nw = wid >> 2;
    const int wo = wid & 3;                 // gate-group stagger offset
    const int c4 = l & 3, q = l >> 2;
    const int b0 = blockIdx.x * TB;

    // ---- copy staged weights into SMEM ----
    {
        const float4* src = (const float4*)g_Bfrag;
        float4* dst = (float4*)(smem + SM_BFRAG);
        for (int i = tid; i < 2560; i += NTHR) dst[i] = src[i];
    }
    for (int i = tid; i < 256; i += NTHR) sF[FI_BC + i] = g_bc[i];
    for (int i = tid; i < 128; i += NTHR) { sF[FI_W2P + i] = g_w2p[i]; sF[FI_MG + i] = g_Mg[i]; }
    if (tid < 4)  sF[FI_M2 + tid] = g_M2[tid];
    if (tid < 2)  { sF[FI_CV + tid] = g_cv[tid]; sF[FI_CG + tid] = g_cg[tid]; }
    if (tid < 32) sF[FI_WSE4 + tid] = g_wse4[tid];
    if (tid < 16) sF[FI_BSE2 + tid] = g_bse2[tid];
    __syncthreads();

    // ---- init H buffer 0 from h0, x0 ----
    {
        u32* Hhi = (u32*)(smem + SM_H);
        u32* Hlo = (u32*)(smem + SM_H + 22528);
        for (int idx = tid; idx < 128 * 40; idx += NTHR) {
            int row = idx / 40, w = idx - row * 40;
            float2 hv = *(const float2*)(h0g + (size_t)(b0 + row) * 64 + 2 * w);
            u32 hw, lw; f16_split(hv.x, hv.y, hw, lw);
            Hhi[row * HROW + w] = hw; Hlo[row * HROW + w] = lw;
        }
        for (int idx = tid; idx < 128 * 8; idx += NTHR) {
            int row = idx >> 3, p = idx & 7;
            float2 tr = *(const float2*)(traj_rel + (size_t)(b0 + row) * 2);
            float4 w4 = *(const float4*)(sF + FI_WSE4 + 4 * p);
            float xa = w4.x * tr.x + w4.y * tr.y + sF[FI_BSE2 + 2 * p];
            float xb = w4.z * tr.x + w4.w * tr.y + sF[FI_BSE2 + 2 * p + 1];
            xa = (xa > 0.f) ? xa : 0.01f * xa;
            xb = (xb > 0.f) ? xb : 0.01f * xb;
            u32 hw, lw; f16_split(xa, xb, hw, lw);
            Hhi[row * HROW + 32 + p] = hw; Hlo[row * HROW + 32 + p] = lw;
        }
    }

    // ---- c-state into registers: creg[gg][m][rh][jj], gate group (gg+wo)&3 ----
    float creg[4][2][2][2];
    #pragma unroll
    for (int gg = 0; gg < 4; gg++) {
        const int g = (gg + wo) & 3;
        #pragma unroll
        for (int m = 0; m < 2; m++)
            #pragma unroll
            for (int rh = 0; rh < 2; rh++) {
                int row = 32 * mw + 16 * m + 8 * rh + q;
                int j = 32 * nw + 8 * g + 2 * c4;
                float2 cv2 = *(const float2*)(c0g + (size_t)(b0 + row) * 64 + j);
                creg[gg][m][rh][0] = cv2.x; creg[gg][m][rh][1] = cv2.y;
            }
    }

    // ---- per-row derived state (nw==0 warps own it) ----
    float goc[4][2], ab[4][2];
    if (nw == 0) {
        #pragma unroll
        for (int m = 0; m < 2; m++)
            #pragma unroll
            for (int rh = 0; rh < 2; rh++) {
                int rl = 2 * m + rh;
                int row = 32 * mw + 16 * m + 8 * rh + q;
                ab[rl][0] = traj_abs[(size_t)(b0 + row) * 2];
                ab[rl][1] = traj_abs[(size_t)(b0 + row) * 2 + 1];
                float s0 = sF[FI_CG], s1 = sF[FI_CG + 1];
                const float* gp = goals + (size_t)(b0 + row) * 64;
                #pragma unroll 8
                for (int k = 0; k < 64; k++) {
                    float gv = gp[k];
                    s0 += sF[FI_MG + k] * gv;
                    s1 += sF[FI_MG + 64 + k] * gv;
                }
                goc[rl][0] = s0; goc[rl][1] = s1;
            }
    }
    __syncthreads();

    const u64* BfragS = (const u64*)(smem + SM_BFRAG);

    for (int s = 0; s < SEQ; s++) {
        const u32* Hhi = (const u32*)(smem + SM_H + (s & 1) * HBUF_BYTES);
        const u32* Hlo = Hhi + 5632;
        u32* Nhi = (u32*)(smem + SM_H + ((s + 1) & 1) * HBUF_BYTES);
        u32* Nlo = Nhi + 5632;

        // ---- load A fragments (hi/lo) ----
        u32 Ahi[2][5][4], Alo[2][5][4];
        #pragma unroll
        for (int m = 0; m < 2; m++) {
            const int rbase = (32 * mw + 16 * m + q) * HROW;
            #pragma unroll
            for (int kc = 0; kc < 5; kc++) {
                int w0 = 8 * kc + c4, w1 = w0 + 4;
                Ahi[m][kc][0] = Hhi[rbase + w0];
                Ahi[m][kc][1] = Hhi[rbase + 8 * HROW + w0];
                Ahi[m][kc][2] = Hhi[rbase + w1];
                Ahi[m][kc][3] = Hhi[rbase + 8 * HROW + w1];
                Alo[m][kc][0] = Hlo[rbase + w0];
                Alo[m][kc][1] = Hlo[rbase + 8 * HROW + w0];
                Alo[m][kc][2] = Hlo[rbase + w1];
                Alo[m][kc][3] = Hlo[rbase + 8 * HROW + w1];
            }
        }

        float rp[4][2] = {};
        #pragma unroll
        for (int gg = 0; gg < 4; gg++) {
            const int g = (gg + wo) & 3;       // actual gate group (staggered)
            float acc[2][4][4] = {};
            #pragma unroll
            for (int kc = 0; kc < 5; kc++) {
                const int fb = ((nw * 4 + g) * 5 + kc) * 4;
                #pragma unroll
                for (int t = 0; t < 4; t++) {
                    u64 bv = BfragS[(u32)(fb + t) * 32 + l];
                    u32 bb0 = (u32)bv, bb1 = (u32)(bv >> 32);
                    #pragma unroll
                    for (int m = 0; m < 2; m++) {
                        mma16816(acc[m][t], Ahi[m][kc], bb0, bb1);
                        mma16816(acc[m][t], Alo[m][kc], bb0, bb1);
                    }
                }
            }
            // ---- epilogue for gate group g ----
            const int jbase = 32 * nw + 8 * g + 2 * c4;
            const float2 bI = *(const float2*)(sF + FI_BC + jbase);
            const float2 bF = *(const float2*)(sF + FI_BC + 64 + jbase);
            const float2 bG = *(const float2*)(sF + FI_BC + 128 + jbase);
            const float2 bO = *(const float2*)(sF + FI_BC + 192 + jbase);
            const float4 w2q = *(const float4*)(sF + FI_W2P + 2 * jbase);
            const int wcol = 16 * nw + 4 * g + c4;
            #pragma unroll
            for (int m = 0; m < 2; m++) {
                #pragma unroll
                for (int rh = 0; rh < 2; rh++) {
                    const int rl = 2 * m + rh;
                    float h0v = lstm_unit(acc[m][0][2 * rh] + bI.x,
                                          acc[m][1][2 * rh] + bF.x,
                                          acc[m][2][2 * rh] + bG.x,
                                          acc[m][3][2 * rh] + bO.x,
                                          creg[gg][m][rh][0]);
                    float h1v = lstm_unit(acc[m][0][2 * rh + 1] + bI.y,
                                          acc[m][1][2 * rh + 1] + bF.y,
                                          acc[m][2][2 * rh + 1] + bG.y,
                                          acc[m][3][2 * rh + 1] + bO.y,
                                          creg[gg][m][rh][1]);
                    rp[rl][0] += w2q.x * h0v + w2q.z * h1v;
                    rp[rl][1] += w2q.y * h0v + w2q.w * h1v;
                    u32 hw, lw; f16_split(h0v, h1v, hw, lw);
                    const int row = 32 * mw + 16 * m + 8 * rh + q;
                    Nhi[row * HROW + wcol] = hw;
                    Nlo[row * HROW + wcol] = lw;
                }
            }
        }

        // ---- rel partial reduction within quads ----
        #pragma unroll
        for (int rl = 0; rl < 4; rl++) {
            #pragma unroll
            for (int ax = 0; ax < 2; ax++) {
                float v = rp[rl][ax];
                v += __shfl_xor_sync(0xFFFFFFFFu, v, 1);
                v += __shfl_xor_sync(0xFFFFFFFFu, v, 2);
                rp[rl][ax] = v;
            }
        }
        if (nw == 1 && c4 == 0) {
            #pragma unroll
            for (int rl = 0; rl < 4; rl++) {
                int row = 32 * mw + 16 * (rl >> 1) + 8 * (rl & 1) + q;
                *(float2*)(sF + FI_RELP + 2 * row) = make_float2(rp[rl][0], rp[rl][1]);
            }
        }
        __syncthreads();   // h' writes + RELP visible

        if (nw == 0) {
            #pragma unroll
            for (int rl = 0; rl < 4; rl++) {
                const int row = 32 * mw + 16 * (rl >> 1) + 8 * (rl & 1) + q;
                float2 pt = *(const float2*)(sF + FI_RELP + 2 * row);
                float r0 = rp[rl][0] + pt.x + sF[FI_CV] + goc[rl][0]
                         + sF[FI_M2] * ab[rl][0] + sF[FI_M2 + 1] * ab[rl][1];
                float r1 = rp[rl][1] + pt.y + sF[FI_CV + 1] + goc[rl][1]
                         + sF[FI_M2 + 2] * ab[rl][0] + sF[FI_M2 + 3] * ab[rl][1];
                if (c4 == 0)
                    *(float2*)(out + ((size_t)s * Btot + b0 + row) * 2) = make_float2(r0, r1);
                ab[rl][0] += r0; ab[rl][1] += r1;
                if (s < SEQ - 1) {
                    #pragma unroll
                    for (int pi = 0; pi < 2; pi++) {
                        int p = c4 + 4 * pi;
                        float4 w4 = *(const float4*)(sF + FI_WSE4 + 4 * p);
                        float xa = w4.x * r0 + w4.y * r1 + sF[FI_BSE2 + 2 * p];
                        float xb = w4.z * r0 + w4.w * r1 + sF[FI_BSE2 + 2 * p + 1];
                        xa = (xa > 0.f) ? xa : 0.01f * xa;
                        xb = (xb > 0.f) ? xb : 0.01f * xb;
                        u32 hw, lw; f16_split(xa, xb, hw, lw);
                        Nhi[row * HROW + 32 + p] = hw;
                        Nlo[row * HROW + 32 + p] = lw;
                    }
                }
            }
        }
        __syncthreads();
    }
}

// ============================================================================
extern "C" void kernel_launch(void* const* d_in, const int* in_sizes, int n_in,
                              void* d_out, int out_size)
{
    const float* traj_abs = (const float*)d_in[0];
    const float* traj_rel = (const float*)d_in[1];
    const float* h0       = (const float*)d_in[2];
    const float* c0       = (const float*)d_in[3];
    const float* goals    = (const float*)d_in[4];
    const float* W_ih     = (const float*)d_in[5];
    const float* W_hh     = (const float*)d_in[6];
    const float* b_ih     = (const float*)d_in[7];
    const float* b_hh     = (const float*)d_in[8];
    const float* W_se     = (const float*)d_in[9];
    const float* b_se     = (const float*)d_in[10];
    const float* W_h2p    = (const float*)d_in[11];
    const float* b_h2p    = (const float*)d_in[12];
    const float* W_goal   = (const float*)d_in[13];
    const float* b_goal   = (const float*)d_in[14];
    const float* W_abs    = (const float*)d_in[15];
    const float* b_abs    = (const float*)d_in[16];

    int B = in_sizes[2] / 64;

    cudaFuncSetAttribute(lstm_main, cudaFuncAttributeMaxDynamicSharedMemorySize, SMEM_BYTES);

    prep_kernel<<<1, NTHR>>>(W_ih, W_hh, b_ih, b_hh, W_h2p, b_h2p,
                             W_goal, b_goal, W_abs, b_abs, W_se, b_se);
    lstm_main<<<B / TB, NTHR, SMEM_BYTES>>>(traj_abs, traj_rel, h0, c0, goals,
                                            (float*)d_out, B);
}

// round 6
// speedup vs baseline: 2.3382x; 1.5732x over previous
#include <cuda_runtime.h>
#include <cuda_fp16.h>
#include <cstdint>

// GoalDecoderLSTM, B=131072, H=64, E=16, SEQ=30 — fp16 HMMA, 16 warps/SM.
// CTA = 64 elems, 8 warps (mw 0..3: 16 rows; nw 0..1: 128 gate-cols), occ 2.
// D[64,256] = A[64,80] @ B[256,80]^T, single fp16 A and B.
// Warp-staggered gate groups, merged-rcp activations, bias folded into acc.

#define TB    64
#define SEQ   30
#define NTHR  256
#define HROW  44

// SMEM byte offsets
#define SM_BFRAG   0                        // 160 frags * 256B = 40960
#define SM_H       40960                    // 2 bufs * 64*44*4 = 2*11264
#define HBUF_BYTES 11264
#define SM_F       (SM_H + 2*HBUF_BYTES)    // 63488
// float indices within sF
#define FI_BC    0      // 256
#define FI_W2P   256    // 128
#define FI_MG    384    // 128
#define FI_M2    512    // 4
#define FI_CV    516    // 2
#define FI_CG    518    // 2
#define FI_WSE4  520    // 32
#define FI_BSE2  552    // 16
#define FI_RELP  568    // 128 (64 rows x 2)
#define SF_FLOATS 696
#define SMEM_BYTES (SM_F + SF_FLOATS*4)     // 66272

typedef uint32_t u32;
typedef unsigned long long u64;

// ---- device staging (prep -> main) ----
__device__ __align__(16) u64 g_Bfrag[160 * 32];   // 40960 B
__device__ float g_bc[256];
__device__ float g_w2p[128];
__device__ float g_Mg[128];
__device__ float g_M2[4];
__device__ float g_cv[2];
__device__ float g_cg[2];
__device__ float g_wse4[32];
__device__ float g_bse2[16];

// ---- helpers ----
__device__ __forceinline__ u32 f16pack(float a, float b) {
    __half2 h = __floats2half2_rn(a, b);    // a -> low, b -> high
    return *(u32*)&h;
}
__device__ __forceinline__ void mma16816(float* d, const u32* a, u32 b0, u32 b1) {
    asm volatile("mma.sync.aligned.m16n8k16.row.col.f32.f16.f16.f32 "
        "{%0,%1,%2,%3}, {%4,%5,%6,%7}, {%8,%9}, {%0,%1,%2,%3};"
        : "+f"(d[0]), "+f"(d[1]), "+f"(d[2]), "+f"(d[3])
        : "r"(a[0]), "r"(a[1]), "r"(a[2]), "r"(a[3]), "r"(b0), "r"(b1));
}
// merged-reciprocal LSTM unit: updates c, returns h. 5 ex2 + 2 rcp.
__device__ __forceinline__ float lstm_unit(float iv, float fv, float gv, float ov, float& cst) {
    float ea = __expf(-iv);
    float eb = __expf(-fv);
    float ed = __expf(-2.0f * fabsf(gv));
    float pa = 1.0f + ea, pb = 1.0f + eb, pd = 1.0f + ed;
    float r1 = __fdividef(1.0f, pa * pb * pd);
    float cn = cst * pa * pd * r1 + copysignf((1.0f - ed) * pb * r1, gv);
    cst = cn;
    float eo = __expf(-ov);
    float ee = __expf(-2.0f * fabsf(cn));
    float r2 = __fdividef(1.0f, (1.0f + eo) * (1.0f + ee));
    return copysignf((1.0f - ee) * r2, cn);
}

// ============================================================================
// Prep: fold small matrices; build B fragments (fp16, mma-fragment order)
// ============================================================================
__global__ void prep_kernel(const float* __restrict__ W_ih, const float* __restrict__ W_hh,
                            const float* __restrict__ b_ih, const float* __restrict__ b_hh,
                            const float* __restrict__ W_h2p, const float* __restrict__ b_h2p,
                            const float* __restrict__ W_goal, const float* __restrict__ b_goal,
                            const float* __restrict__ W_abs, const float* __restrict__ b_abs,
                            const float* __restrict__ W_se, const float* __restrict__ b_se)
{
    int tid = threadIdx.x;
    // frag f = ((nw*4+g)*5+kc)*4+t, lane l
    for (int idx = tid; idx < 160 * 32; idx += NTHR) {
        int f = idx >> 5, l = idx & 31;
        int t = f & 3, kc = (f >> 2) % 5, g = (f / 20) & 3, nw = (f / 80) & 1;
        int jj = l >> 2, c4 = l & 3;
        int j = 32 * nw + 8 * g + jj;
        int row = t * 64 + j;
        int k0 = 16 * kc + 2 * c4;
        float v[4];
        #pragma unroll
        for (int i = 0; i < 4; i++) {
            int k = k0 + (i & 1) + (i >> 1) * 8;
            v[i] = (k < 64) ? W_hh[row * 64 + k] : W_ih[row * 16 + (k - 64)];
        }
        __half2 p0 = __floats2half2_rn(v[0], v[1]);
        __half2 p1 = __floats2half2_rn(v[2], v[3]);
        g_Bfrag[idx] = (u64)*(u32*)&p0 | ((u64)*(u32*)&p1 << 32);
    }
    {
        int j = tid & 63, t = tid >> 6, row = t * 64 + j;
        g_bc[tid] = b_ih[row] + b_hh[row];
    }
    if (tid < 64) {
        g_w2p[2 * tid]     = W_h2p[tid];
        g_w2p[2 * tid + 1] = W_h2p[192 + tid];
    }
    if (tid < 128) {
        int r = tid >> 6, j = tid & 63;
        float s = 0.f;
        for (int m = 0; m < 64; m++) s += W_h2p[r * 192 + 128 + m] * W_goal[m * 64 + j];
        g_Mg[tid] = s;
    }
    if (tid < 4) {
        int r = tid >> 1, c = tid & 1;
        float s = 0.f;
        for (int m = 0; m < 64; m++) s += W_h2p[r * 192 + 64 + m] * W_abs[m * 2 + c];
        g_M2[tid] = s;
    }
    if (tid < 2) {
        float s = b_h2p[tid];
        for (int m = 0; m < 64; m++) s += W_h2p[tid * 192 + 64 + m] * b_abs[m];
        g_cv[tid] = s;
        float s2 = 0.f;
        for (int m = 0; m < 64; m++) s2 += W_h2p[tid * 192 + 128 + m] * b_goal[m];
        g_cg[tid] = s2;
    }
    if (tid < 8) {
        g_wse4[tid * 4 + 0] = W_se[(2 * tid) * 2 + 0];
        g_wse4[tid * 4 + 1] = W_se[(2 * tid) * 2 + 1];
        g_wse4[tid * 4 + 2] = W_se[(2 * tid + 1) * 2 + 0];
        g_wse4[tid * 4 + 3] = W_se[(2 * tid + 1) * 2 + 1];
        g_bse2[tid * 2 + 0] = b_se[2 * tid];
        g_bse2[tid * 2 + 1] = b_se[2 * tid + 1];
    }
}

// ============================================================================
// Main kernel: 64 elems/CTA, 8 warps, 2 CTAs/SM
// ============================================================================
__global__ void __launch_bounds__(NTHR, 2)
lstm_main(const float* __restrict__ traj_abs, const float* __restrict__ traj_rel,
          const float* __restrict__ h0g, const float* __restrict__ c0g,
          const float* __restrict__ goals, float* __restrict__ out, int Btot)
{
    extern __shared__ __align__(16) char smem[];
    float* sF = (float*)(smem + SM_F);
    const int tid = threadIdx.x, l = tid & 31, wid = tid >> 5;
    const int mw = wid & 3, nw = wid >> 2;     // 16-row tile, 128-col half
    const int c4 = l & 3, q = l >> 2;
    const int b0 = blockIdx.x * TB;

    // ---- copy staged weights into SMEM ----
    {
        const float4* src = (const float4*)g_Bfrag;
        float4* dst = (float4*)(smem + SM_BFRAG);
        for (int i = tid; i < 2560; i += NTHR) dst[i] = src[i];
    }
    for (int i = tid; i < 256; i += NTHR) sF[FI_BC + i] = g_bc[i];
    if (tid < 128) { sF[FI_W2P + tid] = g_w2p[tid]; sF[FI_MG + tid] = g_Mg[tid]; }
    if (tid < 4)  sF[FI_M2 + tid] = g_M2[tid];
    if (tid < 2)  { sF[FI_CV + tid] = g_cv[tid]; sF[FI_CG + tid] = g_cg[tid]; }
    if (tid < 32) sF[FI_WSE4 + tid] = g_wse4[tid];
    if (tid < 16) sF[FI_BSE2 + tid] = g_bse2[tid];
    __syncthreads();

    // ---- init H buffer 0 from h0, x0 (fp16x2 words) ----
    {
        u32* H0 = (u32*)(smem + SM_H);
        for (int idx = tid; idx < TB * 32; idx += NTHR) {
            int row = idx >> 5, w = idx & 31;
            float2 hv = *(const float2*)(h0g + (size_t)(b0 + row) * 64 + 2 * w);
            H0[row * HROW + w] = f16pack(hv.x, hv.y);
        }
        for (int idx = tid; idx < TB * 8; idx += NTHR) {
            int row = idx >> 3, p = idx & 7;
            float2 tr = *(const float2*)(traj_rel + (size_t)(b0 + row) * 2);
            float4 w4 = *(const float4*)(sF + FI_WSE4 + 4 * p);
            float xa = w4.x * tr.x + w4.y * tr.y + sF[FI_BSE2 + 2 * p];
            float xb = w4.z * tr.x + w4.w * tr.y + sF[FI_BSE2 + 2 * p + 1];
            xa = (xa > 0.f) ? xa : 0.01f * xa;
            xb = (xb > 0.f) ? xb : 0.01f * xb;
            H0[row * HROW + 32 + p] = f16pack(xa, xb);
        }
    }

    // ---- c-state into registers: creg[gg][rh][jj], gate group (gg+mw)&3 ----
    float creg[4][2][2];
    #pragma unroll
    for (int gg = 0; gg < 4; gg++) {
        const int g = (gg + mw) & 3;
        #pragma unroll
        for (int rh = 0; rh < 2; rh++) {
            int row = 16 * mw + 8 * rh + q;
            int j = 32 * nw + 8 * g + 2 * c4;
            float2 cv2 = *(const float2*)(c0g + (size_t)(b0 + row) * 64 + j);
            creg[gg][rh][0] = cv2.x; creg[gg][rh][1] = cv2.y;
        }
    }

    // ---- per-row derived state (nw==0 warps own rows) ----
    float goc[2][2], ab[2][2];
    if (nw == 0) {
        #pragma unroll
        for (int rh = 0; rh < 2; rh++) {
            int row = 16 * mw + 8 * rh + q;
            ab[rh][0] = traj_abs[(size_t)(b0 + row) * 2];
            ab[rh][1] = traj_abs[(size_t)(b0 + row) * 2 + 1];
            float s0 = sF[FI_CG], s1 = sF[FI_CG + 1];
            const float* gp = goals + (size_t)(b0 + row) * 64;
            #pragma unroll 8
            for (int k = 0; k < 64; k++) {
                float gv = gp[k];
                s0 += sF[FI_MG + k] * gv;
                s1 += sF[FI_MG + 64 + k] * gv;
            }
            goc[rh][0] = s0; goc[rh][1] = s1;
        }
    }
    __syncthreads();

    const u64* BfragS = (const u64*)(smem + SM_BFRAG);

    for (int s = 0; s < SEQ; s++) {
        const u32* H = (const u32*)(smem + SM_H + (s & 1) * HBUF_BYTES);
        u32* N = (u32*)(smem + SM_H + ((s + 1) & 1) * HBUF_BYTES);

        // ---- load A fragments ----
        u32 A[5][4];
        {
            const int rbase = (16 * mw + q) * HROW;
            #pragma unroll
            for (int kc = 0; kc < 5; kc++) {
                int w0 = 8 * kc + c4, w1 = w0 + 4;
                A[kc][0] = H[rbase + w0];
                A[kc][1] = H[rbase + 8 * HROW + w0];
                A[kc][2] = H[rbase + w1];
                A[kc][3] = H[rbase + 8 * HROW + w1];
            }
        }

        float rp[2][2] = {};
        #pragma unroll
        for (int gg = 0; gg < 4; gg++) {
            const int g = (gg + mw) & 3;       // staggered gate group
            const int jbase = 32 * nw + 8 * g + 2 * c4;
            const float2 bI = *(const float2*)(sF + FI_BC + jbase);
            const float2 bF = *(const float2*)(sF + FI_BC + 64 + jbase);
            const float2 bG = *(const float2*)(sF + FI_BC + 128 + jbase);
            const float2 bO = *(const float2*)(sF + FI_BC + 192 + jbase);
            // bias folded into accumulator init
            float acc[4][4] = {
                { bI.x, bI.y, bI.x, bI.y },
                { bF.x, bF.y, bF.x, bF.y },
                { bG.x, bG.y, bG.x, bG.y },
                { bO.x, bO.y, bO.x, bO.y },
            };
            #pragma unroll
            for (int kc = 0; kc < 5; kc++) {
                const int fb = ((nw * 4 + g) * 5 + kc) * 4;
                #pragma unroll
                for (int t = 0; t < 4; t++) {
                    u64 bv = BfragS[(u32)(fb + t) * 32 + l];
                    mma16816(acc[t], A[kc], (u32)bv, (u32)(bv >> 32));
                }
            }
            // ---- epilogue for gate group g ----
            const float4 w2q = *(const float4*)(sF + FI_W2P + 2 * jbase);
            const int wcol = 16 * nw + 4 * g + c4;
            #pragma unroll
            for (int rh = 0; rh < 2; rh++) {
                float h0v = lstm_unit(acc[0][2 * rh], acc[1][2 * rh],
                                      acc[2][2 * rh], acc[3][2 * rh], creg[gg][rh][0]);
                float h1v = lstm_unit(acc[0][2 * rh + 1], acc[1][2 * rh + 1],
                                      acc[2][2 * rh + 1], acc[3][2 * rh + 1], creg[gg][rh][1]);
                rp[rh][0] += w2q.x * h0v + w2q.z * h1v;
                rp[rh][1] += w2q.y * h0v + w2q.w * h1v;
                const int row = 16 * mw + 8 * rh + q;
                N[row * HROW + wcol] = f16pack(h0v, h1v);
            }
        }

        // ---- rel partial reduction within quads ----
        #pragma unroll
        for (int rh = 0; rh < 2; rh++) {
            #pragma unroll
            for (int ax = 0; ax < 2; ax++) {
                float v = rp[rh][ax];
                v += __shfl_xor_sync(0xFFFFFFFFu, v, 1);
                v += __shfl_xor_sync(0xFFFFFFFFu, v, 2);
                rp[rh][ax] = v;
            }
        }
        if (nw == 1 && c4 == 0) {
            #pragma unroll
            for (int rh = 0; rh < 2; rh++) {
                int row = 16 * mw + 8 * rh + q;
                *(float2*)(sF + FI_RELP + 2 * row) = make_float2(rp[rh][0], rp[rh][1]);
            }
        }
        __syncthreads();   // h' writes + RELP visible

        if (nw == 0) {
            #pragma unroll
            for (int rh = 0; rh < 2; rh++) {
                const int row = 16 * mw + 8 * rh + q;
                float2 pt = *(const float2*)(sF + FI_RELP + 2 * row);
                float r0 = rp[rh][0] + pt.x + sF[FI_CV] + goc[rh][0]
                         + sF[FI_M2] * ab[rh][0] + sF[FI_M2 + 1] * ab[rh][1];
                float r1 = rp[rh][1] + pt.y + sF[FI_CV + 1] + goc[rh][1]
                         + sF[FI_M2 + 2] * ab[rh][0] + sF[FI_M2 + 3] * ab[rh][1];
                if (c4 == 0)
                    *(float2*)(out + ((size_t)s * Btot + b0 + row) * 2) = make_float2(r0, r1);
                ab[rh][0] += r0; ab[rh][1] += r1;
                if (s < SEQ - 1) {
                    #pragma unroll
                    for (int pi = 0; pi < 2; pi++) {
                        int p = c4 + 4 * pi;
                        float4 w4 = *(const float4*)(sF + FI_WSE4 + 4 * p);
                        float xa = w4.x * r0 + w4.y * r1 + sF[FI_BSE2 + 2 * p];
                        float xb = w4.z * r0 + w4.w * r1 + sF[FI_BSE2 + 2 * p + 1];
                        xa = (xa > 0.f) ? xa : 0.01f * xa;
                        xb = (xb > 0.f) ? xb : 0.01f * xb;
                        N[row * HROW + 32 + p] = f16pack(xa, xb);
                    }
                }
            }
        }
        __syncthreads();   // x' visible before next step's A loads
    }
}

// ============================================================================
extern "C" void kernel_launch(void* const* d_in, const int* in_sizes, int n_in,
                              void* d_out, int out_size)
{
    const float* traj_abs = (const float*)d_in[0];
    const float* traj_rel = (const float*)d_in[1];
    const float* h0       = (const float*)d_in[2];
    const float* c0       = (const float*)d_in[3];
    const float* goals    = (const float*)d_in[4];
    const float* W_ih     = (const float*)d_in[5];
    const float* W_hh     = (const float*)d_in[6];
    const float* b_ih     = (const float*)d_in[7];
    const float* b_hh     = (const float*)d_in[8];
    const float* W_se     = (const float*)d_in[9];
    const float* b_se     = (const float*)d_in[10];
    const float* W_h2p    = (const float*)d_in[11];
    const float* b_h2p    = (const float*)d_in[12];
    const float* W_goal   = (const float*)d_in[13];
    const float* b_goal   = (const float*)d_in[14];
    const float* W_abs    = (const float*)d_in[15];
    const float* b_abs    = (const float*)d_in[16];

    int B = in_sizes[2] / 64;

    cudaFuncSetAttribute(lstm_main, cudaFuncAttributeMaxDynamicSharedMemorySize, SMEM_BYTES);

    prep_kernel<<<1, NTHR>>>(W_ih, W_hh, b_ih, b_hh, W_h2p, b_h2p,
                             W_goal, b_goal, W_abs, b_abs, W_se, b_se);
    lstm_main<<<B / TB, NTHR, SMEM_BYTES>>>(traj_abs, traj_rel, h0, c0, goals,
                                            (float*)d_out, B);
}

// round 7
// speedup vs baseline: 2.8270x; 1.2091x over previous
#include <cuda_runtime.h>
#include <cuda_fp16.h>
#include <cstdint>

// GoalDecoderLSTM, B=131072, H=64, E=16, SEQ=30 — fp16 HMMA, 16 warps/SM.
// CTA = 64 elems, 8 warps (mw 0..3: 16 rows; nw 0..1: 128 gate-cols), occ 2.
// R7: tanh.approx activations, B frags t-pair interleaved (LDS.128).

#define TB    64
#define SEQ   30
#define NTHR  256
#define HROW  44

// SMEM byte offsets
#define SM_BFRAG   0                        // 160 frags * 256B = 40960
#define SM_H       40960                    // 2 bufs * 64*44*4 = 2*11264
#define HBUF_BYTES 11264
#define SM_F       (SM_H + 2*HBUF_BYTES)    // 63488
// float indices within sF
#define FI_BC    0      // 256
#define FI_W2P   256    // 128
#define FI_MG    384    // 128
#define FI_M2    512    // 4
#define FI_CV    516    // 2
#define FI_CG    518    // 2
#define FI_WSE4  520    // 32
#define FI_BSE2  552    // 16
#define FI_RELP  568    // 128 (64 rows x 2)
#define SF_FLOATS 696
#define SMEM_BYTES (SM_F + SF_FLOATS*4)     // 66272

typedef uint32_t u32;
typedef unsigned long long u64;

// ---- device staging (prep -> main) ----
__device__ __align__(16) u64 g_Bfrag[160 * 32];   // 40960 B, t-pair interleaved
__device__ float g_bc[256];
__device__ float g_w2p[128];
__device__ float g_Mg[128];
__device__ float g_M2[4];
__device__ float g_cv[2];
__device__ float g_cg[2];
__device__ float g_wse4[32];
__device__ float g_bse2[16];

// ---- helpers ----
__device__ __forceinline__ u32 f16pack(float a, float b) {
    __half2 h = __floats2half2_rn(a, b);    // a -> low, b -> high
    return *(u32*)&h;
}
__device__ __forceinline__ void mma16816(float* d, const u32* a, u32 b0, u32 b1) {
    asm volatile("mma.sync.aligned.m16n8k16.row.col.f32.f16.f16.f32 "
        "{%0,%1,%2,%3}, {%4,%5,%6,%7}, {%8,%9}, {%0,%1,%2,%3};"
        : "+f"(d[0]), "+f"(d[1]), "+f"(d[2]), "+f"(d[3])
        : "r"(a[0]), "r"(a[1]), "r"(a[2]), "r"(a[3]), "r"(b0), "r"(b1));
}
__device__ __forceinline__ float tanh_hw(float x) {
    float r; asm("tanh.approx.f32 %0, %1;" : "=f"(r) : "f"(x)); return r;
}
// hardware-tanh LSTM unit: updates c, returns h. 5 MUFU + ~8 FMA.
__device__ __forceinline__ float lstm_unit(float iv, float fv, float gv, float ov, float& cst) {
    float si = fmaf(0.5f, tanh_hw(0.5f * iv), 0.5f);
    float sf = fmaf(0.5f, tanh_hw(0.5f * fv), 0.5f);
    float tg = tanh_hw(gv);
    float so = fmaf(0.5f, tanh_hw(0.5f * ov), 0.5f);
    float cn = fmaf(sf, cst, si * tg);
    cst = cn;
    return so * tanh_hw(cn);
}

// ============================================================================
// Prep: fold small matrices; build B fragments (fp16, t-pair interleaved)
// ============================================================================
__global__ void prep_kernel(const float* __restrict__ W_ih, const float* __restrict__ W_hh,
                            const float* __restrict__ b_ih, const float* __restrict__ b_hh,
                            const float* __restrict__ W_h2p, const float* __restrict__ b_h2p,
                            const float* __restrict__ W_goal, const float* __restrict__ b_goal,
                            const float* __restrict__ W_abs, const float* __restrict__ b_abs,
                            const float* __restrict__ W_se, const float* __restrict__ b_se)
{
    int tid = threadIdx.x;
    // logical frag f = ((nw*4+g)*5+kc)*4+t, lane l
    for (int idx = tid; idx < 160 * 32; idx += NTHR) {
        int f = idx >> 5, l = idx & 31;
        int t = f & 3, kc = (f >> 2) % 5, g = (f / 20) & 3, nw = (f / 80) & 1;
        int jj = l >> 2, c4 = l & 3;
        int j = 32 * nw + 8 * g + jj;
        int row = t * 64 + j;
        int k0 = 16 * kc + 2 * c4;
        float v[4];
        #pragma unroll
        for (int i = 0; i < 4; i++) {
            int k = k0 + (i & 1) + (i >> 1) * 8;
            v[i] = (k < 64) ? W_hh[row * 64 + k] : W_ih[row * 16 + (k - 64)];
        }
        __half2 p0 = __floats2half2_rn(v[0], v[1]);
        __half2 p1 = __floats2half2_rn(v[2], v[3]);
        // t-pair interleave: (t, t+1) adjacent for LDS.128
        int fbase = (((nw * 4 + g) * 5 + kc) * 2 + (t >> 1));
        g_Bfrag[fbase * 64 + 2 * l + (t & 1)] = (u64)*(u32*)&p0 | ((u64)*(u32*)&p1 << 32);
    }
    {
        int j = tid & 63, t = tid >> 6, row = t * 64 + j;
        g_bc[tid] = b_ih[row] + b_hh[row];
    }
    if (tid < 64) {
        g_w2p[2 * tid]     = W_h2p[tid];
        g_w2p[2 * tid + 1] = W_h2p[192 + tid];
    }
    if (tid < 128) {
        int r = tid >> 6, j = tid & 63;
        float s = 0.f;
        for (int m = 0; m < 64; m++) s += W_h2p[r * 192 + 128 + m] * W_goal[m * 64 + j];
        g_Mg[tid] = s;
    }
    if (tid < 4) {
        int r = tid >> 1, c = tid & 1;
        float s = 0.f;
        for (int m = 0; m < 64; m++) s += W_h2p[r * 192 + 64 + m] * W_abs[m * 2 + c];
        g_M2[tid] = s;
    }
    if (tid < 2) {
        float s = b_h2p[tid];
        for (int m = 0; m < 64; m++) s += W_h2p[tid * 192 + 64 + m] * b_abs[m];
        g_cv[tid] = s;
        float s2 = 0.f;
        for (int m = 0; m < 64; m++) s2 += W_h2p[tid * 192 + 128 + m] * b_goal[m];
        g_cg[tid] = s2;
    }
    if (tid < 8) {
        g_wse4[tid * 4 + 0] = W_se[(2 * tid) * 2 + 0];
        g_wse4[tid * 4 + 1] = W_se[(2 * tid) * 2 + 1];
        g_wse4[tid * 4 + 2] = W_se[(2 * tid + 1) * 2 + 0];
        g_wse4[tid * 4 + 3] = W_se[(2 * tid + 1) * 2 + 1];
        g_bse2[tid * 2 + 0] = b_se[2 * tid];
        g_bse2[tid * 2 + 1] = b_se[2 * tid + 1];
    }
}

// ============================================================================
// Main kernel: 64 elems/CTA, 8 warps, 2 CTAs/SM
// ============================================================================
__global__ void __launch_bounds__(NTHR, 2)
lstm_main(const float* __restrict__ traj_abs, const float* __restrict__ traj_rel,
          const float* __restrict__ h0g, const float* __restrict__ c0g,
          const float* __restrict__ goals, float* __restrict__ out, int Btot)
{
    extern __shared__ __align__(16) char smem[];
    float* sF = (float*)(smem + SM_F);
    const int tid = threadIdx.x, l = tid & 31, wid = tid >> 5;
    const int mw = wid & 3, nw = wid >> 2;     // 16-row tile, 128-col half
    const int c4 = l & 3, q = l >> 2;
    const int b0 = blockIdx.x * TB;

    // ---- copy staged weights into SMEM ----
    {
        const float4* src = (const float4*)g_Bfrag;
        float4* dst = (float4*)(smem + SM_BFRAG);
        for (int i = tid; i < 2560; i += NTHR) dst[i] = src[i];
    }
    for (int i = tid; i < 256; i += NTHR) sF[FI_BC + i] = g_bc[i];
    if (tid < 128) { sF[FI_W2P + tid] = g_w2p[tid]; sF[FI_MG + tid] = g_Mg[tid]; }
    if (tid < 4)  sF[FI_M2 + tid] = g_M2[tid];
    if (tid < 2)  { sF[FI_CV + tid] = g_cv[tid]; sF[FI_CG + tid] = g_cg[tid]; }
    if (tid < 32) sF[FI_WSE4 + tid] = g_wse4[tid];
    if (tid < 16) sF[FI_BSE2 + tid] = g_bse2[tid];
    __syncthreads();

    // ---- init H buffer 0 from h0, x0 (fp16x2 words) ----
    {
        u32* H0 = (u32*)(smem + SM_H);
        for (int idx = tid; idx < TB * 32; idx += NTHR) {
            int row = idx >> 5, w = idx & 31;
            float2 hv = *(const float2*)(h0g + (size_t)(b0 + row) * 64 + 2 * w);
            H0[row * HROW + w] = f16pack(hv.x, hv.y);
        }
        for (int idx = tid; idx < TB * 8; idx += NTHR) {
            int row = idx >> 3, p = idx & 7;
            float2 tr = *(const float2*)(traj_rel + (size_t)(b0 + row) * 2);
            float4 w4 = *(const float4*)(sF + FI_WSE4 + 4 * p);
            float xa = w4.x * tr.x + w4.y * tr.y + sF[FI_BSE2 + 2 * p];
            float xb = w4.z * tr.x + w4.w * tr.y + sF[FI_BSE2 + 2 * p + 1];
            xa = (xa > 0.f) ? xa : 0.01f * xa;
            xb = (xb > 0.f) ? xb : 0.01f * xb;
            H0[row * HROW + 32 + p] = f16pack(xa, xb);
        }
    }

    // ---- c-state into registers: creg[gg][rh][jj], gate group (gg+mw)&3 ----
    float creg[4][2][2];
    #pragma unroll
    for (int gg = 0; gg < 4; gg++) {
        const int g = (gg + mw) & 3;
        #pragma unroll
        for (int rh = 0; rh < 2; rh++) {
            int row = 16 * mw + 8 * rh + q;
            int j = 32 * nw + 8 * g + 2 * c4;
            float2 cv2 = *(const float2*)(c0g + (size_t)(b0 + row) * 64 + j);
            creg[gg][rh][0] = cv2.x; creg[gg][rh][1] = cv2.y;
        }
    }

    // ---- per-row derived state (nw==0 warps own rows) ----
    float goc[2][2], ab[2][2];
    if (nw == 0) {
        #pragma unroll
        for (int rh = 0; rh < 2; rh++) {
            int row = 16 * mw + 8 * rh + q;
            ab[rh][0] = traj_abs[(size_t)(b0 + row) * 2];
            ab[rh][1] = traj_abs[(size_t)(b0 + row) * 2 + 1];
            float s0 = sF[FI_CG], s1 = sF[FI_CG + 1];
            const float* gp = goals + (size_t)(b0 + row) * 64;
            #pragma unroll 8
            for (int k = 0; k < 64; k++) {
                float gv = gp[k];
                s0 += sF[FI_MG + k] * gv;
                s1 += sF[FI_MG + 64 + k] * gv;
            }
            goc[rh][0] = s0; goc[rh][1] = s1;
        }
    }
    __syncthreads();

    const u64* BfragS = (const u64*)(smem + SM_BFRAG);

    for (int s = 0; s < SEQ; s++) {
        const u32* H = (const u32*)(smem + SM_H + (s & 1) * HBUF_BYTES);
        u32* N = (u32*)(smem + SM_H + ((s + 1) & 1) * HBUF_BYTES);

        // ---- load A fragments ----
        u32 A[5][4];
        {
            const int rbase = (16 * mw + q) * HROW;
            #pragma unroll
            for (int kc = 0; kc < 5; kc++) {
                int w0 = 8 * kc + c4, w1 = w0 + 4;
                A[kc][0] = H[rbase + w0];
                A[kc][1] = H[rbase + 8 * HROW + w0];
                A[kc][2] = H[rbase + w1];
                A[kc][3] = H[rbase + 8 * HROW + w1];
            }
        }

        float rp[2][2] = {};
        #pragma unroll
        for (int gg = 0; gg < 4; gg++) {
            const int g = (gg + mw) & 3;       // staggered gate group
            const int jbase = 32 * nw + 8 * g + 2 * c4;
            const float2 bI = *(const float2*)(sF + FI_BC + jbase);
            const float2 bF = *(const float2*)(sF + FI_BC + 64 + jbase);
            const float2 bG = *(const float2*)(sF + FI_BC + 128 + jbase);
            const float2 bO = *(const float2*)(sF + FI_BC + 192 + jbase);
            // bias folded into accumulator init
            float acc[4][4] = {
                { bI.x, bI.y, bI.x, bI.y },
                { bF.x, bF.y, bF.x, bF.y },
                { bG.x, bG.y, bG.x, bG.y },
                { bO.x, bO.y, bO.x, bO.y },
            };
            const u64* Bp = BfragS + (u32)((nw * 4 + g) * 5) * 128 + 2 * l;
            #pragma unroll
            for (int kc = 0; kc < 5; kc++) {
                ulonglong2 b01 = *(const ulonglong2*)(Bp + kc * 128);
                ulonglong2 b23 = *(const ulonglong2*)(Bp + kc * 128 + 64);
                mma16816(acc[0], A[kc], (u32)b01.x, (u32)(b01.x >> 32));
                mma16816(acc[1], A[kc], (u32)b01.y, (u32)(b01.y >> 32));
                mma16816(acc[2], A[kc], (u32)b23.x, (u32)(b23.x >> 32));
                mma16816(acc[3], A[kc], (u32)b23.y, (u32)(b23.y >> 32));
            }
            // ---- epilogue for gate group g ----
            const float4 w2q = *(const float4*)(sF + FI_W2P + 2 * jbase);
            const int wcol = 16 * nw + 4 * g + c4;
            #pragma unroll
            for (int rh = 0; rh < 2; rh++) {
                float h0v = lstm_unit(acc[0][2 * rh], acc[1][2 * rh],
                                      acc[2][2 * rh], acc[3][2 * rh], creg[gg][rh][0]);
                float h1v = lstm_unit(acc[0][2 * rh + 1], acc[1][2 * rh + 1],
                                      acc[2][2 * rh + 1], acc[3][2 * rh + 1], creg[gg][rh][1]);
                rp[rh][0] += w2q.x * h0v + w2q.z * h1v;
                rp[rh][1] += w2q.y * h0v + w2q.w * h1v;
                const int row = 16 * mw + 8 * rh + q;
                N[row * HROW + wcol] = f16pack(h0v, h1v);
            }
        }

        // ---- rel partial reduction within quads ----
        #pragma unroll
        for (int rh = 0; rh < 2; rh++) {
            #pragma unroll
            for (int ax = 0; ax < 2; ax++) {
                float v = rp[rh][ax];
                v += __shfl_xor_sync(0xFFFFFFFFu, v, 1);
                v += __shfl_xor_sync(0xFFFFFFFFu, v, 2);
                rp[rh][ax] = v;
            }
        }
        if (nw == 1 && c4 == 0) {
            #pragma unroll
            for (int rh = 0; rh < 2; rh++) {
                int row = 16 * mw + 8 * rh + q;
                *(float2*)(sF + FI_RELP + 2 * row) = make_float2(rp[rh][0], rp[rh][1]);
            }
        }
        __syncthreads();   // h' writes + RELP visible

        if (nw == 0) {
            #pragma unroll
            for (int rh = 0; rh < 2; rh++) {
                const int row = 16 * mw + 8 * rh + q;
                float2 pt = *(const float2*)(sF + FI_RELP + 2 * row);
                float r0 = rp[rh][0] + pt.x + sF[FI_CV] + goc[rh][0]
                         + sF[FI_M2] * ab[rh][0] + sF[FI_M2 + 1] * ab[rh][1];
                float r1 = rp[rh][1] + pt.y + sF[FI_CV + 1] + goc[rh][1]
                         + sF[FI_M2 + 2] * ab[rh][0] + sF[FI_M2 + 3] * ab[rh][1];
                if (c4 == 0)
                    *(float2*)(out + ((size_t)s * Btot + b0 + row) * 2) = make_float2(r0, r1);
                ab[rh][0] += r0; ab[rh][1] += r1;
                if (s < SEQ - 1) {
                    #pragma unroll
                    for (int pi = 0; pi < 2; pi++) {
                        int p = c4 + 4 * pi;
                        float4 w4 = *(const float4*)(sF + FI_WSE4 + 4 * p);
                        float xa = w4.x * r0 + w4.y * r1 + sF[FI_BSE2 + 2 * p];
                        float xb = w4.z * r0 + w4.w * r1 + sF[FI_BSE2 + 2 * p + 1];
                        xa = (xa > 0.f) ? xa : 0.01f * xa;
                        xb = (xb > 0.f) ? xb : 0.01f * xb;
                        N[row * HROW + 32 + p] = f16pack(xa, xb);
                    }
                }
            }
        }
        __syncthreads();   // x' visible before next step's A loads
    }
}

// ============================================================================
extern "C" void kernel_launch(void* const* d_in, const int* in_sizes, int n_in,
                              void* d_out, int out_size)
{
    const float* traj_abs = (const float*)d_in[0];
    const float* traj_rel = (const float*)d_in[1];
    const float* h0       = (const float*)d_in[2];
    const float* c0       = (const float*)d_in[3];
    const float* goals    = (const float*)d_in[4];
    const float* W_ih     = (const float*)d_in[5];
    const float* W_hh     = (const float*)d_in[6];
    const float* b_ih     = (const float*)d_in[7];
    const float* b_hh     = (const float*)d_in[8];
    const float* W_se     = (const float*)d_in[9];
    const float* b_se     = (const float*)d_in[10];
    const float* W_h2p    = (const float*)d_in[11];
    const float* b_h2p    = (const float*)d_in[12];
    const float* W_goal   = (const float*)d_in[13];
    const float* b_goal   = (const float*)d_in[14];
    const float* W_abs    = (const float*)d_in[15];
    const float* b_abs    = (const float*)d_in[16];

    int B = in_sizes[2] / 64;

    cudaFuncSetAttribute(lstm_main, cudaFuncAttributeMaxDynamicSharedMemorySize, SMEM_BYTES);

    prep_kernel<<<1, NTHR>>>(W_ih, W_hh, b_ih, b_hh, W_h2p, b_h2p,
                             W_goal, b_goal, W_abs, b_abs, W_se, b_se);
    lstm_main<<<B / TB, NTHR, SMEM_BYTES>>>(traj_abs, traj_rel, h0, c0, goals,
                                            (float*)d_out, B);
}

// round 8
// speedup vs baseline: 3.0201x; 1.0683x over previous
#include <cuda_runtime.h>
#include <cuda_fp16.h>
#include <cstdint>

// GoalDecoderLSTM, B=131072, H=64, E=16, SEQ=30 — fp16 HMMA.
// R8: B weights register-resident. CTA = 64 elems, 8 warps, occ 2.
// Warp w owns gate-cols [32w,32w+32) (j in [8w,8w+8), all 4 gates), all 64 rows
// (4 m-tiles). B slice = 20 frags = 40 regs, loaded once. A re-read per m-tile
// from permuted fp16x2 H image (LDS.64 pairs). Cross-warp rel via RELP in SMEM.

#define TB    64
#define SEQ   30
#define NTHR  256
#define HROW  40

// SMEM layout
#define SM_H       0                        // 2 bufs * 64*40*4 = 2*10240
#define HBUF_BYTES 10240
#define SM_F       (2*HBUF_BYTES)           // 20480
// float indices within sF
#define FI_BC    0      // 256
#define FI_W2P   256    // 128
#define FI_MG    384    // 128
#define FI_M2    512    // 4
#define FI_CV    516    // 2
#define FI_CG    518    // 2
#define FI_WSE4  520    // 32
#define FI_BSE2  552    // 16
#define FI_RELP  568    // 8 warps * 64 rows * 2 = 1024
#define FI_AB    1592   // 128
#define FI_GOC   1720   // 128
#define SF_FLOATS 1848
#define SMEM_BYTES (SM_F + SF_FLOATS*4)     // 27872

typedef uint32_t u32;
typedef unsigned long long u64;

// ---- device staging (prep -> main) ----
__device__ __align__(16) u64 g_Bfrag[160 * 32];   // frag f = wid*20 + kc*4 + t
__device__ float g_bc[256];
__device__ float g_w2p[128];
__device__ float g_Mg[128];
__device__ float g_M2[4];
__device__ float g_cv[2];
__device__ float g_cg[2];
__device__ float g_wse4[32];
__device__ float g_bse2[16];

// ---- helpers ----
__device__ __forceinline__ u32 f16pack(float a, float b) {
    __half2 h = __floats2half2_rn(a, b);    // a -> low, b -> high
    return *(u32*)&h;
}
__device__ __forceinline__ void mma16816(float* d, const u32* a, u32 b0, u32 b1) {
    asm volatile("mma.sync.aligned.m16n8k16.row.col.f32.f16.f16.f32 "
        "{%0,%1,%2,%3}, {%4,%5,%6,%7}, {%8,%9}, {%0,%1,%2,%3};"
        : "+f"(d[0]), "+f"(d[1]), "+f"(d[2]), "+f"(d[3])
        : "r"(a[0]), "r"(a[1]), "r"(a[2]), "r"(a[3]), "r"(b0), "r"(b1));
}
__device__ __forceinline__ float tanh_hw(float x) {
    float r; asm("tanh.approx.f32 %0, %1;" : "=f"(r) : "f"(x)); return r;
}
__device__ __forceinline__ float lstm_unit(float iv, float fv, float gv, float ov, float& cst) {
    float si = fmaf(0.5f, tanh_hw(0.5f * iv), 0.5f);
    float sf = fmaf(0.5f, tanh_hw(0.5f * fv), 0.5f);
    float tg = tanh_hw(gv);
    float so = fmaf(0.5f, tanh_hw(0.5f * ov), 0.5f);
    float cn = fmaf(sf, cst, si * tg);
    cst = cn;
    return so * tanh_hw(cn);
}
// word permutation within each 8-word block: logical p -> 2*(p&3)+((p>>2)&1)
__device__ __forceinline__ int permw(int v) {
    return (v & ~7) + 2 * (v & 3) + ((v >> 2) & 1);
}

// ============================================================================
// Prep: fold small matrices; build B fragments (fp16, per-warp-slice order)
// ============================================================================
__global__ void prep_kernel(const float* __restrict__ W_ih, const float* __restrict__ W_hh,
                            const float* __restrict__ b_ih, const float* __restrict__ b_hh,
                            const float* __restrict__ W_h2p, const float* __restrict__ b_h2p,
                            const float* __restrict__ W_goal, const float* __restrict__ b_goal,
                            const float* __restrict__ W_abs, const float* __restrict__ b_abs,
                            const float* __restrict__ W_se, const float* __restrict__ b_se)
{
    int tid = threadIdx.x;
    // frag f = w*20 + kc*4 + t  (w = warp slice 0..7, j in [8w, 8w+8))
    for (int idx = tid; idx < 160 * 32; idx += NTHR) {
        int f = idx >> 5, l = idx & 31;
        int w = f / 20, r = f % 20, kc = r >> 2, t = r & 3;
        int jj = l >> 2, c4 = l & 3;
        int j = 8 * w + jj;
        int row = t * 64 + j;
        int k0 = 16 * kc + 2 * c4;
        float v[4];
        #pragma unroll
        for (int i = 0; i < 4; i++) {
            int k = k0 + (i & 1) + (i >> 1) * 8;
            v[i] = (k < 64) ? W_hh[row * 64 + k] : W_ih[row * 16 + (k - 64)];
        }
        __half2 p0 = __floats2half2_rn(v[0], v[1]);
        __half2 p1 = __floats2half2_rn(v[2], v[3]);
        g_Bfrag[idx] = (u64)*(u32*)&p0 | ((u64)*(u32*)&p1 << 32);
    }
    {
        int j = tid & 63, t = tid >> 6, row = t * 64 + j;
        g_bc[tid] = b_ih[row] + b_hh[row];
    }
    if (tid < 64) {
        g_w2p[2 * tid]     = W_h2p[tid];
        g_w2p[2 * tid + 1] = W_h2p[192 + tid];
    }
    if (tid < 128) {
        int r = tid >> 6, j = tid & 63;
        float s = 0.f;
        for (int m = 0; m < 64; m++) s += W_h2p[r * 192 + 128 + m] * W_goal[m * 64 + j];
        g_Mg[tid] = s;
    }
    if (tid < 4) {
        int r = tid >> 1, c = tid & 1;
        float s = 0.f;
        for (int m = 0; m < 64; m++) s += W_h2p[r * 192 + 64 + m] * W_abs[m * 2 + c];
        g_M2[tid] = s;
    }
    if (tid < 2) {
        float s = b_h2p[tid];
        for (int m = 0; m < 64; m++) s += W_h2p[tid * 192 + 64 + m] * b_abs[m];
        g_cv[tid] = s;
        float s2 = 0.f;
        for (int m = 0; m < 64; m++) s2 += W_h2p[tid * 192 + 128 + m] * b_goal[m];
        g_cg[tid] = s2;
    }
    if (tid < 8) {
        g_wse4[tid * 4 + 0] = W_se[(2 * tid) * 2 + 0];
        g_wse4[tid * 4 + 1] = W_se[(2 * tid) * 2 + 1];
        g_wse4[tid * 4 + 2] = W_se[(2 * tid + 1) * 2 + 0];
        g_wse4[tid * 4 + 3] = W_se[(2 * tid + 1) * 2 + 1];
        g_bse2[tid * 2 + 0] = b_se[2 * tid];
        g_bse2[tid * 2 + 1] = b_se[2 * tid + 1];
    }
}

// ============================================================================
// Main kernel: 64 elems/CTA, 8 warps, 2 CTAs/SM, B in registers
// ============================================================================
__global__ void __launch_bounds__(NTHR, 2)
lstm_main(const float* __restrict__ traj_abs, const float* __restrict__ traj_rel,
          const float* __restrict__ h0g, const float* __restrict__ c0g,
          const float* __restrict__ goals, float* __restrict__ out, int Btot)
{
    extern __shared__ __align__(16) char smem[];
    float* sF = (float*)(smem + SM_F);
    const int tid = threadIdx.x, l = tid & 31, wid = tid >> 5;
    const int c4 = l & 3, q = l >> 2;
    const int b0 = blockIdx.x * TB;

    // ---- fill sF from staging ----
    for (int i = tid; i < 256; i += NTHR) sF[FI_BC + i] = g_bc[i];
    if (tid < 128) { sF[FI_W2P + tid] = g_w2p[tid]; sF[FI_MG + tid] = g_Mg[tid]; }
    if (tid < 4)  sF[FI_M2 + tid] = g_M2[tid];
    if (tid < 2)  { sF[FI_CV + tid] = g_cv[tid]; sF[FI_CG + tid] = g_cg[tid]; }
    if (tid < 32) sF[FI_WSE4 + tid] = g_wse4[tid];
    if (tid < 16) sF[FI_BSE2 + tid] = g_bse2[tid];
    __syncthreads();

    // ---- B fragments into registers (persistent) ----
    u64 Breg[5][4];
    {
        const u64* gB = g_Bfrag + (size_t)wid * 20 * 32 + l;
        #pragma unroll
        for (int kc = 0; kc < 5; kc++)
            #pragma unroll
            for (int t = 0; t < 4; t++)
                Breg[kc][t] = gB[(kc * 4 + t) * 32];
    }
    // per-warp-lane constants: biases + w2 pairs for j0 = 8*wid + 2*c4
    const int j0 = 8 * wid + 2 * c4;
    const float2 bI = *(const float2*)(sF + FI_BC + j0);
    const float2 bF = *(const float2*)(sF + FI_BC + 64 + j0);
    const float2 bG = *(const float2*)(sF + FI_BC + 128 + j0);
    const float2 bO = *(const float2*)(sF + FI_BC + 192 + j0);
    const float4 w2q = *(const float4*)(sF + FI_W2P + 2 * j0);
    const int wp = permw(4 * wid + c4);     // h' store word position

    // ---- init H buffer 0 (permuted fp16x2 words) ----
    {
        u32* H0 = (u32*)(smem + SM_H);
        for (int idx = tid; idx < TB * 32; idx += NTHR) {
            int row = idx >> 5, w = idx & 31;
            float2 hv = *(const float2*)(h0g + (size_t)(b0 + row) * 64 + 2 * w);
            H0[row * HROW + permw(w)] = f16pack(hv.x, hv.y);
        }
        for (int idx = tid; idx < TB * 8; idx += NTHR) {
            int row = idx >> 3, p = idx & 7;
            float2 tr = *(const float2*)(traj_rel + (size_t)(b0 + row) * 2);
            float4 w4 = *(const float4*)(sF + FI_WSE4 + 4 * p);
            float xa = w4.x * tr.x + w4.y * tr.y + sF[FI_BSE2 + 2 * p];
            float xb = w4.z * tr.x + w4.w * tr.y + sF[FI_BSE2 + 2 * p + 1];
            xa = (xa > 0.f) ? xa : 0.01f * xa;
            xb = (xb > 0.f) ? xb : 0.01f * xb;
            H0[row * HROW + 32 + 2 * (p & 3) + (p >> 2)] = f16pack(xa, xb);
        }
    }

    // ---- c-state: creg[m][rh][jj], rows 16m+8rh+q, j = j0+jj ----
    float creg[4][2][2];
    #pragma unroll
    for (int m = 0; m < 4; m++)
        #pragma unroll
        for (int rh = 0; rh < 2; rh++) {
            int row = 16 * m + 8 * rh + q;
            float2 cv2 = *(const float2*)(c0g + (size_t)(b0 + row) * 64 + j0);
            creg[m][rh][0] = cv2.x; creg[m][rh][1] = cv2.y;
        }

    // ---- row-owner derived state -> SMEM (tid < 64, row = tid) ----
    if (tid < TB) {
        const int row = tid;
        sF[FI_AB + 2 * row]     = traj_abs[(size_t)(b0 + row) * 2];
        sF[FI_AB + 2 * row + 1] = traj_abs[(size_t)(b0 + row) * 2 + 1];
        float s0 = sF[FI_CG], s1 = sF[FI_CG + 1];
        const float* gp = goals + (size_t)(b0 + row) * 64;
        #pragma unroll 8
        for (int k = 0; k < 64; k++) {
            float gv = gp[k];
            s0 += sF[FI_MG + k] * gv;
            s1 += sF[FI_MG + 64 + k] * gv;
        }
        sF[FI_GOC + 2 * row] = s0; sF[FI_GOC + 2 * row + 1] = s1;
    }
    __syncthreads();

    #pragma unroll 1
    for (int s = 0; s < SEQ; s++) {
        const u32* H = (const u32*)(smem + SM_H + (s & 1) * HBUF_BYTES);
        u32* N = (u32*)(smem + SM_H + ((s + 1) & 1) * HBUF_BYTES);

        #pragma unroll
        for (int m = 0; m < 4; m++) {
            // ---- A fragments for rows [16m, 16m+16) ----
            u32 A[5][4];
            const int r0b = (16 * m + q) * HROW + 2 * c4;
            const int r1b = r0b + 8 * HROW;
            #pragma unroll
            for (int kc = 0; kc < 5; kc++) {
                u64 v0 = *(const u64*)(H + r0b + 8 * kc);
                u64 v1 = *(const u64*)(H + r1b + 8 * kc);
                A[kc][0] = (u32)v0; A[kc][2] = (u32)(v0 >> 32);
                A[kc][1] = (u32)v1; A[kc][3] = (u32)(v1 >> 32);
            }
            // ---- MMA: bias-initialized accumulators ----
            float acc[4][4] = {
                { bI.x, bI.y, bI.x, bI.y },
                { bF.x, bF.y, bF.x, bF.y },
                { bG.x, bG.y, bG.x, bG.y },
                { bO.x, bO.y, bO.x, bO.y },
            };
            #pragma unroll
            for (int kc = 0; kc < 5; kc++)
                #pragma unroll
                for (int t = 0; t < 4; t++)
                    mma16816(acc[t], A[kc], (u32)Breg[kc][t], (u32)(Breg[kc][t] >> 32));

            // ---- epilogue ----
            float rpm[2][2];
            #pragma unroll
            for (int rh = 0; rh < 2; rh++) {
                float h0v = lstm_unit(acc[0][2 * rh], acc[1][2 * rh],
                                      acc[2][2 * rh], acc[3][2 * rh], creg[m][rh][0]);
                float h1v = lstm_unit(acc[0][2 * rh + 1], acc[1][2 * rh + 1],
                                      acc[2][2 * rh + 1], acc[3][2 * rh + 1], creg[m][rh][1]);
                rpm[rh][0] = w2q.x * h0v + w2q.z * h1v;
                rpm[rh][1] = w2q.y * h0v + w2q.w * h1v;
                const int row = 16 * m + 8 * rh + q;
                N[row * HROW + wp] = f16pack(h0v, h1v);
            }
            // quad butterfly -> warp partial for this warp's 8 j's
            #pragma unroll
            for (int rh = 0; rh < 2; rh++) {
                #pragma unroll
                for (int ax = 0; ax < 2; ax++) {
                    float v = rpm[rh][ax];
                    v += __shfl_xor_sync(0xFFFFFFFFu, v, 1);
                    v += __shfl_xor_sync(0xFFFFFFFFu, v, 2);
                    rpm[rh][ax] = v;
                }
            }
            if (c4 == 0) {
                #pragma unroll
                for (int rh = 0; rh < 2; rh++) {
                    int row = 16 * m + 8 * rh + q;
                    *(float2*)(sF + FI_RELP + 2 * (wid * 64 + row)) =
                        make_float2(rpm[rh][0], rpm[rh][1]);
                }
            }
        }
        __syncthreads();   // h' + RELP visible

        // ---- rel finalization: one thread per row ----
        if (tid < TB) {
            const int row = tid;
            float a0 = sF[FI_AB + 2 * row], a1 = sF[FI_AB + 2 * row + 1];
            float r0 = sF[FI_CV] + sF[FI_GOC + 2 * row]
                     + sF[FI_M2] * a0 + sF[FI_M2 + 1] * a1;
            float r1 = sF[FI_CV + 1] + sF[FI_GOC + 2 * row + 1]
                     + sF[FI_M2 + 2] * a0 + sF[FI_M2 + 3] * a1;
            #pragma unroll
            for (int w = 0; w < 8; w++) {
                float2 pw = *(const float2*)(sF + FI_RELP + 2 * (w * 64 + row));
                r0 += pw.x; r1 += pw.y;
            }
            *(float2*)(out + ((size_t)s * Btot + b0 + row) * 2) = make_float2(r0, r1);
            sF[FI_AB + 2 * row] = a0 + r0;
            sF[FI_AB + 2 * row + 1] = a1 + r1;
            if (s < SEQ - 1) {
                #pragma unroll
                for (int p = 0; p < 8; p++) {
                    float4 w4 = *(const float4*)(sF + FI_WSE4 + 4 * p);
                    float xa = w4.x * r0 + w4.y * r1 + sF[FI_BSE2 + 2 * p];
                    float xb = w4.z * r0 + w4.w * r1 + sF[FI_BSE2 + 2 * p + 1];
                    xa = (xa > 0.f) ? xa : 0.01f * xa;
                    xb = (xb > 0.f) ? xb : 0.01f * xb;
                    N[row * HROW + 32 + 2 * (p & 3) + (p >> 2)] = f16pack(xa, xb);
                }
            }
        }
        __syncthreads();   // N fully updated before next step's A loads
    }
}

// ============================================================================
extern "C" void kernel_launch(void* const* d_in, const int* in_sizes, int n_in,
                              void* d_out, int out_size)
{
    const float* traj_abs = (const float*)d_in[0];
    const float* traj_rel = (const float*)d_in[1];
    const float* h0       = (const float*)d_in[2];
    const float* c0       = (const float*)d_in[3];
    const float* goals    = (const float*)d_in[4];
    const float* W_ih     = (const float*)d_in[5];
    const float* W_hh     = (const float*)d_in[6];
    const float* b_ih     = (const float*)d_in[7];
    const float* b_hh     = (const float*)d_in[8];
    const float* W_se     = (const float*)d_in[9];
    const float* b_se     = (const float*)d_in[10];
    const float* W_h2p    = (const float*)d_in[11];
    const float* b_h2p    = (const float*)d_in[12];
    const float* W_goal   = (const float*)d_in[13];
    const float* b_goal   = (const float*)d_in[14];
    const float* W_abs    = (const float*)d_in[15];
    const float* b_abs    = (const float*)d_in[16];

    int B = in_sizes[2] / 64;

    cudaFuncSetAttribute(lstm_main, cudaFuncAttributeMaxDynamicSharedMemorySize, SMEM_BYTES);

    prep_kernel<<<1, NTHR>>>(W_ih, W_hh, b_ih, b_hh, W_h2p, b_h2p,
                             W_goal, b_goal, W_abs, b_abs, W_se, b_se);
    lstm_main<<<B / TB, NTHR, SMEM_BYTES>>>(traj_abs, traj_rel, h0, c0, goals,
                                            (float*)d_out, B);
}